// round 3
// baseline (speedup 1.0000x reference)
#include <cuda_runtime.h>
#include <math.h>

// Problem shape is fixed: N = 16384.
#define N_ELEM  16384
#define TN      128                         // tile dimension (rows=cols=threads)
#define NTILES  (N_ELEM / TN)               // 128
#define NBLOCKS (NTILES * (NTILES + 1) / 2) // 8256 upper-triangle tiles

// Scratch for deterministic two-stage reduction (no cudaMalloc allowed).
__device__ float g_partials[NBLOCKS];

__device__ __forceinline__ float ex2f(float x) {
    float y; asm("ex2.approx.f32 %0, %1;" : "=f"(y) : "f"(x)); return y;
}
__device__ __forceinline__ float rcpf(float x) {
    float y; asm("rcp.approx.f32 %0, %1;" : "=f"(y) : "f"(x)); return y;
}

// One block = one TN x TN tile (I,J) of the upper triangle (I <= J).
// Computes  sum_{i in tile I, j in tile J} sigmoid(p_i * p_j) * |t_i - t_j|.
// Diagonal tiles (I==J) are computed full and scaled by 0.5: the diagonal
// itself contributes 0 (|t_i - t_i| = 0) and the tile is symmetric.
__global__ __launch_bounds__(TN) void pair_tile_kernel(
    const float* __restrict__ yt, const float* __restrict__ yp)
{
    __shared__ float ts[TN];
    __shared__ float qs[TN];
    __shared__ float red[TN];

    // Invert linear triangular block index k -> (I, J), I <= J.
    // offset(I) = I*NTILES - I*(I-1)/2
    const int k = blockIdx.x;
    const float disc = 2.0f * (float)NTILES + 1.0f;
    int I = (int)((disc - sqrtf(disc * disc - 8.0f * (float)k)) * 0.5f);
    if (I < 0) I = 0;
    if (I >= NTILES) I = NTILES - 1;
    while (((I + 1) * NTILES - ((I + 1) * I) / 2) <= k) ++I;
    while ((I * NTILES - (I * (I - 1)) / 2) > k) --I;
    const int J = I + (k - (I * NTILES - (I * (I - 1)) / 2));

    const int tid = threadIdx.x;

    // Stage column tile: t_j and q_j = -log2(e) * p_j  (so ex2(p_i*q_j) = exp(-p_i*p_j)).
    const int jg = J * TN + tid;
    ts[tid] = yt[jg];
    qs[tid] = yp[jg] * (-1.4426950408889634f);

    // This thread's row.
    const int ig = I * TN + tid;
    const float pi = yp[ig];
    const float ti = yt[ig];
    __syncthreads();

    // 4 independent accumulator chains for MUFU/FMA latency hiding.
    float a0 = 0.f, a1 = 0.f, a2 = 0.f, a3 = 0.f;
    #pragma unroll 8
    for (int j = 0; j < TN; j += 4) {
        const float e0 = ex2f(pi * qs[j + 0]);
        const float e1 = ex2f(pi * qs[j + 1]);
        const float e2 = ex2f(pi * qs[j + 2]);
        const float e3 = ex2f(pi * qs[j + 3]);
        const float s0 = rcpf(1.0f + e0);
        const float s1 = rcpf(1.0f + e1);
        const float s2 = rcpf(1.0f + e2);
        const float s3 = rcpf(1.0f + e3);
        a0 += s0 * fabsf(ti - ts[j + 0]);
        a1 += s1 * fabsf(ti - ts[j + 1]);
        a2 += s2 * fabsf(ti - ts[j + 2]);
        a3 += s3 * fabsf(ti - ts[j + 3]);
    }

    red[tid] = (a0 + a1) + (a2 + a3);
    __syncthreads();
    #pragma unroll
    for (int s = TN / 2; s > 0; s >>= 1) {
        if (tid < s) red[tid] += red[tid + s];
        __syncthreads();
    }
    if (tid == 0) {
        g_partials[k] = (I == J) ? 0.5f * red[0] : red[0];
    }
}

// Deterministic final reduction in double; writes -S / N^2.
__global__ void reduce_kernel(float* __restrict__ out)
{
    __shared__ double sred[256];
    const int tid = threadIdx.x;
    double s = 0.0;
    for (int i = tid; i < NBLOCKS; i += 256) s += (double)g_partials[i];
    sred[tid] = s;
    __syncthreads();
    #pragma unroll
    for (int w = 128; w > 0; w >>= 1) {
        if (tid < w) sred[tid] += sred[tid + w];
        __syncthreads();
    }
    if (tid == 0) {
        const double n2 = (double)N_ELEM * (double)N_ELEM;
        out[0] = (float)(-sred[0] / n2);
    }
}

extern "C" void kernel_launch(void* const* d_in, const int* in_sizes, int n_in,
                              void* d_out, int out_size)
{
    const float* yt = (const float*)d_in[0];  // y_true
    const float* yp = (const float*)d_in[1];  // y_pred
    float* out = (float*)d_out;

    pair_tile_kernel<<<NBLOCKS, TN>>>(yt, yp);
    reduce_kernel<<<1, 256>>>(out);
}